// round 15
// baseline (speedup 1.0000x reference)
#include <cuda_runtime.h>
#include <cuda_bf16.h>

#define BATCH 8192
#define TMAX  2048
#define ROWSTRIDE (TMAX + 1)   // 2049 ints per row (last element is T)
#define TILE 256               // 16 elements per lane x 16 lanes (half-warp)

// Register-resident layered LUT, one entry per lane (shared by both halves):
//   lane k holds entry k; entry 0 = identity; layer v (v=1..4) at base 2^v-1,
//   entry e = product of v consecutive per-obs matrices, v = floor(log2(e+1)),
//   obs bits = (e+1) - 2^v (chronologically first = LSB). Entries 0..30 used.
// float4 = (c00, c01, c10, c11); alpha' = C * alpha.

__device__ __forceinline__ float4 lut_get(const float4 mine, int e) {
    float4 r;
    r.x = __shfl_sync(0xFFFFFFFFu, mine.x, e);
    r.y = __shfl_sync(0xFFFFFFFFu, mine.y, e);
    r.z = __shfl_sync(0xFFFFFFFFu, mine.z, e);
    r.w = __shfl_sync(0xFFFFFFFFu, mine.w, e);
    return r;
}

__device__ __forceinline__ float4 mmul(const float4 L, const float4 R) {
    // matrix product L * R (L applied later in time)
    float4 o;
    o.x = L.x * R.x + L.y * R.z;
    o.y = L.x * R.y + L.y * R.w;
    o.z = L.z * R.x + L.w * R.z;
    o.w = L.z * R.y + L.w * R.w;
    return o;
}

// 16 observations -> one 2x2 product via 4 nibble lookups + 3 matmuls.
// rem = number of valid leading elements (0..16); rest become identity.
__device__ __forceinline__ float4 chunk16(const float4 mine,
                                          int n0, int n1, int n2, int n3, int rem) {
    int r0 = rem;       r0 = r0 < 0 ? 0 : (r0 > 4 ? 4 : r0);
    int r1 = rem - 4;   r1 = r1 < 0 ? 0 : (r1 > 4 ? 4 : r1);
    int r2 = rem - 8;   r2 = r2 < 0 ? 0 : (r2 > 4 ? 4 : r2);
    int r3 = rem - 12;  r3 = r3 < 0 ? 0 : (r3 > 4 ? 4 : r3);
    const int m0 = (1 << r0) - 1, m1 = (1 << r1) - 1;
    const int m2 = (1 << r2) - 1, m3 = (1 << r3) - 1;
    const float4 L0 = lut_get(mine, m0 + (n0 & m0));
    const float4 L1 = lut_get(mine, m1 + (n1 & m1));
    const float4 L2 = lut_get(mine, m2 + (n2 & m2));
    const float4 L3 = lut_get(mine, m3 + (n3 & m3));
    return mmul(mmul(L3, L2), mmul(L1, L0));
}

// Ordered reduce over a 16-lane segment (segment-lane 0 earliest); result on
// segment-lane 0. Fold into r (valid on segment-lane 0), return r's sum.
__device__ __forceinline__ float reduce16_fold(float4 C, float4& r, int hl) {
    #pragma unroll
    for (int d = 1; d < 16; d <<= 1) {
        float4 u;
        u.x = __shfl_down_sync(0xFFFFFFFFu, C.x, d, 16);
        u.y = __shfl_down_sync(0xFFFFFFFFu, C.y, d, 16);
        u.z = __shfl_down_sync(0xFFFFFFFFu, C.z, d, 16);
        u.w = __shfl_down_sync(0xFFFFFFFFu, C.w, d, 16);
        if (hl + d < 16) C = mmul(u, C);   // u is LATER in time
    }
    r = mmul(C, r);                         // authoritative on hl==0 only
    return r.x + r.y + r.z + r.w;           // nonneg: ==0 <=> product is zero
}

__global__ __launch_bounds__(128, 10)
void hmm_fwd_kernel(const int* __restrict__ xin,
                    const float* __restrict__ prior_l,
                    const float* __restrict__ trans_l,
                    const float* __restrict__ emis_l,
                    float* __restrict__ out) {
    const int tid  = threadIdx.x;
    const int wid  = tid >> 5;
    const int lane = tid & 31;
    const int hl   = lane & 15;                // lane within half-warp
    const int half = lane >> 4;                // which row of the pair
    const int row_id = (blockIdx.x * 4 + wid) * 2 + half;

    const int* __restrict__ row = xin + (size_t)row_id * ROWSTRIDE;

    // ---- issue all loads first; latency hides under the constant build ----
    const int T  = row[TMAX];
    const int x0 = row[0];
    const int mis = (row_id + 1) & 3;          // row base ≡ (row_id+1) mod 4 ints
    const int t0  = 1 + ((4 - mis) & 3);       // 16B-aligned start, in [1,4]
    const int pk1 = (t0 > 1) ? row[1] : 0;
    const int pk2 = (t0 > 2) ? row[2] : 0;
    const int pk3 = (t0 > 3) ? row[3] : 0;

    const int pos0 = t0 + (hl << 4);           // <= 244: +16 always in storage
    const int4* p = (const int4*)(row + pos0);
    const int4 q0 = p[0];
    const int4 q1 = p[1];
    const int4 q2 = p[2];
    const int4 q3 = p[3];

    // ---- softmax constants via sigmoid form (2-class softmax) ----
    const float p0f = __fdividef(1.0f, 1.0f + __expf(prior_l[1] - prior_l[0]));
    const float p1f = 1.0f - p0f;

    const float A00 = __fdividef(1.0f, 1.0f + __expf(trans_l[1] - trans_l[0]));
    const float A01 = 1.0f - A00;
    const float A10 = __fdividef(1.0f, 1.0f + __expf(trans_l[3] - trans_l[2]));
    const float A11 = 1.0f - A10;

    const float E00 = __fdividef(1.0f, 1.0f + __expf(emis_l[1] - emis_l[0]));
    const float E01 = 1.0f - E00;
    const float E10 = __fdividef(1.0f, 1.0f + __expf(emis_l[3] - emis_l[2]));
    const float E11 = 1.0f - E10;

    const float Ma00 = E00 * A00, Ma01 = E00 * A10, Ma10 = E10 * A01, Ma11 = E10 * A11;
    const float Mb00 = E01 * A00, Mb01 = E01 * A10, Mb10 = E11 * A01, Mb11 = E11 * A11;

    // ---- each lane builds LUT entry 'lane' in registers (shared per warp) ----
    float4 mine = make_float4(1.f, 0.f, 0.f, 1.f);   // lane 0 identity; 31 unused
    if (lane >= 1 && lane <= 30) {
        const int n = lane + 1;
        const int v = 31 - __clz(n);           // layer
        const int idx = n - (1 << v);          // obs bits
        float c00 = 1.f, c01 = 0.f, c10 = 0.f, c11 = 1.f;
        for (int i = 0; i < v; ++i) {
            const int b = (idx >> i) & 1;
            const float m00 = b ? Mb00 : Ma00, m01 = b ? Mb01 : Ma01;
            const float m10 = b ? Mb10 : Ma10, m11 = b ? Mb11 : Ma11;
            const float s00 = m00 * c00 + m01 * c10;
            const float s01 = m00 * c01 + m01 * c11;
            const float s10 = m10 * c00 + m11 * c10;
            const float s11 = m10 * c01 + m11 * c11;
            c00 = s00; c01 = s01; c10 = s10; c11 = s11;
        }
        mine = make_float4(c00, c01, c10, c11);
    }

    // ---- peel elements [1, min(t0,T)) with a single layered lookup ----
    const int pe = t0 < T ? t0 : T;            // peel length = pe-1, in [0,3]
    const int pidx  = pk1 + 2 * pk2 + 4 * pk3;
    const int pmask = (1 << (pe - 1)) - 1;
    float4 r = lut_get(mine, pmask + (pidx & pmask));

    // ---- first tile: 256 steps per half-warp, unconditional (rem-masked) ----
    {
        const int n0 = q0.x | (q0.y << 1) | (q0.z << 2) | (q0.w << 3);
        const int n1 = q1.x | (q1.y << 1) | (q1.z << 2) | (q1.w << 3);
        const int n2 = q2.x | (q2.y << 1) | (q2.z << 2) | (q2.w << 3);
        const int n3 = q3.x | (q3.y << 1) | (q3.z << 2) | (q3.w << 3);
        int rem = T - pos0;
        rem = rem < 0 ? 0 : (rem > 16 ? 16 : rem);
        const float4 C = chunk16(mine, n0, n1, n2, n3, rem);
        float sloc = reduce16_fold(C, r, hl);
        float sum = __shfl_sync(0xFFFFFFFFu, sloc, 0, 16);   // segment-lane 0

        // ---- later tiles: essentially never run (underflow break) ----
        int s = t0 + TILE;
        while (__any_sync(0xFFFFFFFFu, (s < T) && (sum != 0.0f))) {
            const int pos = s + (hl << 4);
            int4 a0 = make_int4(0,0,0,0), a1 = a0, a2 = a0, a3 = a0;
            if (pos < T) {
                if (pos + 16 <= ROWSTRIDE) {
                    const int4* pp = (const int4*)(row + pos);
                    a0 = pp[0]; a1 = pp[1]; a2 = pp[2]; a3 = pp[3];
                } else {                        // tail at the very row end
                    const int v = T - pos;      // <= 14 here
                    a0.x = row[pos];
                    if (v > 1)  a0.y = row[pos + 1];
                    if (v > 2)  a0.z = row[pos + 2];
                    if (v > 3)  a0.w = row[pos + 3];
                    if (v > 4)  a1.x = row[pos + 4];
                    if (v > 5)  a1.y = row[pos + 5];
                    if (v > 6)  a1.z = row[pos + 6];
                    if (v > 7)  a1.w = row[pos + 7];
                    if (v > 8)  a2.x = row[pos + 8];
                    if (v > 9)  a2.y = row[pos + 9];
                    if (v > 10) a2.z = row[pos + 10];
                    if (v > 11) a2.w = row[pos + 11];
                    if (v > 12) a3.x = row[pos + 12];
                    if (v > 13) a3.y = row[pos + 13];
                }
            }
            const int b0 = a0.x | (a0.y << 1) | (a0.z << 2) | (a0.w << 3);
            const int b1 = a1.x | (a1.y << 1) | (a1.z << 2) | (a1.w << 3);
            const int b2 = a2.x | (a2.y << 1) | (a2.z << 2) | (a2.w << 3);
            const int b3 = a3.x | (a3.y << 1) | (a3.z << 2) | (a3.w << 3);
            int rem2 = T - pos;
            rem2 = rem2 < 0 ? 0 : (rem2 > 16 ? 16 : rem2);
            const float4 C2 = chunk16(mine, b0, b1, b2, b3, rem2);
            sloc = reduce16_fold(C2, r, hl);
            sum = __shfl_sync(0xFFFFFFFFu, sloc, 0, 16);
            s += TILE;
        }
    }

    if (hl == 0) {
        const float al0 = (x0 ? E01 : E00) * p0f;
        const float al1 = (x0 ? E11 : E10) * p1f;
        // out = 1^T * P * alpha0 = (col0 sum)*al0 + (col1 sum)*al1
        out[row_id] = (r.x + r.z) * al0 + (r.y + r.w) * al1;
    }
}

extern "C" void kernel_launch(void* const* d_in, const int* in_sizes, int n_in,
                              void* d_out, int out_size) {
    const int*   xin     = (const int*)d_in[0];
    const float* prior_l = (const float*)d_in[1];
    const float* trans_l = (const float*)d_in[2];
    const float* emis_l  = (const float*)d_in[3];
    float* out = (float*)d_out;

    const int blocks = BATCH / 8;      // 1024 blocks, 4 warps, 2 rows per warp
    hmm_fwd_kernel<<<blocks, 128>>>(xin, prior_l, trans_l, emis_l, out);
}